// round 10
// baseline (speedup 1.0000x reference)
#include <cuda_runtime.h>
#include <math.h>

// Problem dims
#define Tt 1024
#define Bb 64
#define Ii 256
#define Hh 512
#define Oo 128

// Recurrent kernel grid: 32 layer-0 CTAs (16 cols each), 64 layer-1 CTAs (8 cols each)
#define G_CTAS 96
#define NL0 32

// ---------------- device scratch (no runtime allocation allowed) ----------------
__device__ float g_xproj[(size_t)Tt * Bb * Hh];   // 128 MB: x@W_ih0^T + b_ih0 + b_hh0, [t][b][h]
__device__ float g_h0[2][Bb * Hh];                // double-buffered layer-0 hidden
__device__ float g_h1[2][Bb * Hh];                // double-buffered layer-1 hidden
__device__ unsigned g_cnt;                        // barrier arrival counter (stays 0 between launches)
__device__ unsigned g_gen;                        // barrier generation (monotonic across launches)

// ---------------- grid barrier (96 co-resident CTAs, sense via generation) ------
__device__ __forceinline__ unsigned ld_acq(const unsigned* p) {
    unsigned v;
    asm volatile("ld.acquire.gpu.u32 %0, [%1];" : "=r"(v) : "l"(p) : "memory");
    return v;
}

__device__ __forceinline__ void grid_barrier(unsigned& target) {
    __syncthreads();
    if (threadIdx.x == 0) {
        __threadfence();                                  // publish this CTA's stores
        unsigned a = atomicAdd(&g_cnt, 1u);
        if (a == G_CTAS - 1u) {
            g_cnt = 0u;                                   // reset BEFORE releasing
            __threadfence();
            atomicAdd(&g_gen, 1u);                        // release
        } else {
            while ((int)(ld_acq(&g_gen) - target) < 0) { __nanosleep(64); }
        }
    }
    __syncthreads();
    target++;
}

// =================================================================================
// Kernel 1: xproj[t][b][j] = sum_i x[b][t][i] * W_ih0[j][i] + b_ih0[j] + b_hh0[j]
// grid (8 n-tiles, 1024 t), 256 threads. K-chunked smem tiles (<=48KB static).
// =================================================================================
__global__ void __launch_bounds__(256) xproj_kernel(
    const float* __restrict__ x, const float* __restrict__ W,
    const float* __restrict__ bih, const float* __restrict__ bhh)
{
    __shared__ float xs[64 * 68];   // [b][k]  pad 68 (bank stride 4)
    __shared__ float ws[64 * 68];   // [k][nl] pad 68

    const int t   = blockIdx.y;
    const int n0  = blockIdx.x * 64;
    const int tid = threadIdx.x;
    const int tx  = tid & 15;       // n micro
    const int ty  = tid >> 4;       // m micro
    const int mi0 = ty * 4;
    const int ni0 = tx * 4;

    float acc[4][4] = {};

    for (int kc = 0; kc < 4; ++kc) {
        const int k0 = kc * 64;
        // load x tile: 64 b x 64 k  (1024 float4)
        for (int idx = tid; idx < 1024; idx += 256) {
            int b  = idx >> 4;
            int c4 = idx & 15;
            float4 v = *reinterpret_cast<const float4*>(
                x + ((size_t)b * Tt + t) * Ii + k0 + c4 * 4);
            *reinterpret_cast<float4*>(xs + b * 68 + c4 * 4) = v;
        }
        // load W tile transposed: ws[k][nl] = W[(n0+nl)][k0+k]
        for (int idx = tid; idx < 1024; idx += 256) {
            int nl = idx >> 4;
            int c4 = idx & 15;
            float4 v = *reinterpret_cast<const float4*>(
                W + (size_t)(n0 + nl) * Ii + k0 + c4 * 4);
            int k = c4 * 4;
            ws[(k + 0) * 68 + nl] = v.x;
            ws[(k + 1) * 68 + nl] = v.y;
            ws[(k + 2) * 68 + nl] = v.z;
            ws[(k + 3) * 68 + nl] = v.w;
        }
        __syncthreads();
        #pragma unroll 8
        for (int k = 0; k < 64; ++k) {
            float4 wv = *reinterpret_cast<const float4*>(ws + k * 68 + ni0);
            float x0 = xs[(mi0 + 0) * 68 + k];
            float x1 = xs[(mi0 + 1) * 68 + k];
            float x2 = xs[(mi0 + 2) * 68 + k];
            float x3 = xs[(mi0 + 3) * 68 + k];
            acc[0][0] += x0 * wv.x; acc[0][1] += x0 * wv.y; acc[0][2] += x0 * wv.z; acc[0][3] += x0 * wv.w;
            acc[1][0] += x1 * wv.x; acc[1][1] += x1 * wv.y; acc[1][2] += x1 * wv.z; acc[1][3] += x1 * wv.w;
            acc[2][0] += x2 * wv.x; acc[2][1] += x2 * wv.y; acc[2][2] += x2 * wv.z; acc[2][3] += x2 * wv.w;
            acc[3][0] += x3 * wv.x; acc[3][1] += x3 * wv.y; acc[3][2] += x3 * wv.z; acc[3][3] += x3 * wv.w;
        }
        __syncthreads();
    }

    float4 bias;
    bias.x = bih[n0 + ni0 + 0] + bhh[n0 + ni0 + 0];
    bias.y = bih[n0 + ni0 + 1] + bhh[n0 + ni0 + 1];
    bias.z = bih[n0 + ni0 + 2] + bhh[n0 + ni0 + 2];
    bias.w = bih[n0 + ni0 + 3] + bhh[n0 + ni0 + 3];
    #pragma unroll
    for (int i = 0; i < 4; ++i) {
        float4 o;
        o.x = acc[i][0] + bias.x;
        o.y = acc[i][1] + bias.y;
        o.z = acc[i][2] + bias.z;
        o.w = acc[i][3] + bias.w;
        *reinterpret_cast<float4*>(
            g_xproj + ((size_t)t * Bb + (mi0 + i)) * Hh + n0 + ni0) = o;
    }
}

// =================================================================================
// Kernel 2: persistent recurrent scan. One grid barrier per phase.
// Phase k (k=1..1024): L0 CTAs compute h0(k) = tanh(xproj[k-1] + h0(k-1)@W_hh0^T)
// Phase k (k=2..1025): L1 CTAs compute h1(k-1) = tanh(h0(k-1)@W_ih1^T + h1(k-2)@W_hh1^T + b)
// =================================================================================
__global__ void __launch_bounds__(512, 1) rnn_kernel(
    const float* __restrict__ h_init,
    const float* __restrict__ W_hh0,
    const float* __restrict__ W_ih1, const float* __restrict__ b_ih1,
    const float* __restrict__ W_hh1, const float* __restrict__ b_hh1)
{
    __shared__ float Wsm[8192];   // L0: [512][16], L1: [1024][8]   (k-major)
    __shared__ float red[4096];   // partial-sum reduction buffer

    const int tid  = threadIdx.x;
    const int cta  = blockIdx.x;
    const bool isL0 = (cta < NL0);

    unsigned target = ld_acq(&g_gen) + 1u;   // stable between launches

    // ---- load weight slice (k-major in smem) ----
    if (isL0) {
        const int j0 = cta * 16;
        for (int e = tid; e < 512 * 16; e += 512) {
            int k = e >> 4, jl = e & 15;
            Wsm[e] = W_hh0[(size_t)(j0 + jl) * Hh + k];
        }
    } else {
        const int j0 = (cta - NL0) * 8;
        for (int e = tid; e < 1024 * 8; e += 512) {
            int k = e >> 3, jl = e & 7;
            Wsm[e] = (k < 512) ? W_ih1[(size_t)(j0 + jl) * Hh + k]
                               : W_hh1[(size_t)(j0 + jl) * Hh + (k - 512)];
        }
    }
    // ---- init state buffers from h0 input (graph replays re-init every launch) ----
    for (int i = cta * 512 + tid; i < Bb * Hh; i += G_CTAS * 512) {
        g_h0[0][i] = h_init[i];
        g_h1[0][i] = h_init[Bb * Hh + i];
    }
    __syncthreads();
    grid_barrier(target);   // barrier #1: init complete

    if (isL0) {
        const int j0 = cta * 16;
        const int t7 = tid & 127;
        const int ks = tid >> 7;          // k-split 0..3 (128 k each)
        const int jq = t7 & 3;            // 4 j-groups of 4 cols
        const int bp = t7 >> 2;           // 0..31 -> b = bp, bp+32
        const int kb = ks * 128;
        const float* wbase = Wsm + kb * 16 + jq * 4;

        for (int k = 1; k <= Tt; ++k) {
            const float* hprev = g_h0[(k - 1) & 1];
            float*       hout  = g_h0[k & 1];
            const float* ha = hprev + bp * Hh + kb;
            const float* hb = hprev + (bp + 32) * Hh + kb;
            float acc[8] = {0.f,0.f,0.f,0.f,0.f,0.f,0.f,0.f};
            #pragma unroll 4
            for (int kk = 0; kk < 128; kk += 4) {
                float4 va = __ldcg(reinterpret_cast<const float4*>(ha + kk));
                float4 vb = __ldcg(reinterpret_cast<const float4*>(hb + kk));
                const float* wr = wbase + kk * 16;
                float4 w0 = *reinterpret_cast<const float4*>(wr);
                float4 w1 = *reinterpret_cast<const float4*>(wr + 16);
                float4 w2 = *reinterpret_cast<const float4*>(wr + 32);
                float4 w3 = *reinterpret_cast<const float4*>(wr + 48);
                acc[0] += va.x*w0.x + va.y*w1.x + va.z*w2.x + va.w*w3.x;
                acc[1] += va.x*w0.y + va.y*w1.y + va.z*w2.y + va.w*w3.y;
                acc[2] += va.x*w0.z + va.y*w1.z + va.z*w2.z + va.w*w3.z;
                acc[3] += va.x*w0.w + va.y*w1.w + va.z*w2.w + va.w*w3.w;
                acc[4] += vb.x*w0.x + vb.y*w1.x + vb.z*w2.x + vb.w*w3.x;
                acc[5] += vb.x*w0.y + vb.y*w1.y + vb.z*w2.y + vb.w*w3.y;
                acc[6] += vb.x*w0.z + vb.y*w1.z + vb.z*w2.z + vb.w*w3.z;
                acc[7] += vb.x*w0.w + vb.y*w1.w + vb.z*w2.w + vb.w*w3.w;
            }
            #pragma unroll
            for (int a = 0; a < 8; ++a) red[ks * 1024 + t7 * 8 + a] = acc[a];
            __syncthreads();
            const int t = k - 1;
            #pragma unroll
            for (int r = 0; r < 2; ++r) {
                int o = tid + r * 512;    // 1024 outputs
                float s = red[o] + red[1024 + o] + red[2048 + o] + red[3072 + o];
                int bpp  = o >> 5;
                int jqq  = (o >> 3) & 3;
                int bsel = (o >> 2) & 1;
                int jc   = o & 3;
                int b    = bpp + (bsel << 5);
                int col  = j0 + jqq * 4 + jc;
                float v  = s + g_xproj[((size_t)t * Bb + b) * Hh + col];
                hout[b * Hh + col] = tanhf(v);
            }
            grid_barrier(target);
        }
        grid_barrier(target);   // phase T+1 (layer-1 finishes), L0 idle
    } else {
        const int j0 = (cta - NL0) * 8;
        const int t6 = tid & 63;
        const int ks = tid >> 6;          // k-split 0..7 (128 k each; 0..3 -> h0, 4..7 -> h1)
        const int jq = t6 & 1;            // 2 j-groups of 4 cols
        const int bp = t6 >> 1;           // 0..31
        const int kb = (ks & 3) * 128;
        const bool useH0 = (ks < 4);
        const float* wbase = Wsm + (ks * 128) * 8 + jq * 4;
        const float bsum = b_ih1[j0 + (t6 & 7)] ? 0.f : 0.f; // (placeholder removed below)
        (void)bsum;

        grid_barrier(target);   // phase 1: nothing for layer 1 yet

        for (int k = 2; k <= Tt + 1; ++k) {
            const float* h0cur  = g_h0[(k - 1) & 1];   // h0(k-1)
            const float* h1prev = g_h1[k & 1];         // h1(k-2)
            float*       hout   = g_h1[(k - 1) & 1];   // h1(k-1)
            const float* hsrc = useH0 ? h0cur : h1prev;
            const float* ha = hsrc + bp * Hh + kb;
            const float* hb = hsrc + (bp + 32) * Hh + kb;
            float acc[8] = {0.f,0.f,0.f,0.f,0.f,0.f,0.f,0.f};
            #pragma unroll 4
            for (int kk = 0; kk < 128; kk += 4) {
                float4 va = __ldcg(reinterpret_cast<const float4*>(ha + kk));
                float4 vb = __ldcg(reinterpret_cast<const float4*>(hb + kk));
                const float* wr = wbase + kk * 8;
                float4 w0 = *reinterpret_cast<const float4*>(wr);
                float4 w1 = *reinterpret_cast<const float4*>(wr + 8);
                float4 w2 = *reinterpret_cast<const float4*>(wr + 16);
                float4 w3 = *reinterpret_cast<const float4*>(wr + 24);
                acc[0] += va.x*w0.x + va.y*w1.x + va.z*w2.x + va.w*w3.x;
                acc[1] += va.x*w0.y + va.y*w1.y + va.z*w2.y + va.w*w3.y;
                acc[2] += va.x*w0.z + va.y*w1.z + va.z*w2.z + va.w*w3.z;
                acc[3] += va.x*w0.w + va.y*w1.w + va.z*w2.w + va.w*w3.w;
                acc[4] += vb.x*w0.x + vb.y*w1.x + vb.z*w2.x + vb.w*w3.x;
                acc[5] += vb.x*w0.y + vb.y*w1.y + vb.z*w2.y + vb.w*w3.y;
                acc[6] += vb.x*w0.z + vb.y*w1.z + vb.z*w2.z + vb.w*w3.z;
                acc[7] += vb.x*w0.w + vb.y*w1.w + vb.z*w2.w + vb.w*w3.w;
            }
            #pragma unroll
            for (int a = 0; a < 8; ++a) red[ks * 512 + t6 * 8 + a] = acc[a];
            __syncthreads();
            {
                int o = tid;   // 512 outputs
                float s = 0.f;
                #pragma unroll
                for (int q = 0; q < 8; ++q) s += red[q * 512 + o];
                int bpp  = o >> 4;
                int jqq  = (o >> 3) & 1;
                int bsel = (o >> 2) & 1;
                int jc   = o & 3;
                int b    = bpp + (bsel << 5);
                int col  = j0 + jqq * 4 + jc;
                float v  = s + b_ih1[col] + b_hh1[col];
                hout[b * Hh + col] = tanhf(v);
            }
            grid_barrier(target);
        }
    }
}

// =================================================================================
// Kernel 3: out[b][o] = h1_final[b] . W_out[o] + b_out[o]   (h1 final is parity 0)
// =================================================================================
__global__ void __launch_bounds__(128) head_kernel(
    const float* __restrict__ W_out, const float* __restrict__ b_out,
    float* __restrict__ out)
{
    const int b = blockIdx.x;      // 64
    const int o = threadIdx.x;     // 128
    const float* h = g_h1[0] + b * Hh;
    const float* w = W_out + (size_t)o * Hh;
    float acc = 0.f;
    #pragma unroll 8
    for (int k = 0; k < Hh; k += 4) {
        float4 hv = *reinterpret_cast<const float4*>(h + k);
        float4 wv = *reinterpret_cast<const float4*>(w + k);
        acc += hv.x * wv.x + hv.y * wv.y + hv.z * wv.z + hv.w * wv.w;
    }
    out[b * Oo + o] = acc + b_out[o];
}

// =================================================================================
extern "C" void kernel_launch(void* const* d_in, const int* in_sizes, int n_in,
                              void* d_out, int out_size)
{
    (void)in_sizes; (void)n_in; (void)out_size;
    const float* x      = (const float*)d_in[0];
    const float* h0     = (const float*)d_in[1];
    const float* W_ih0  = (const float*)d_in[2];
    const float* b_ih0  = (const float*)d_in[3];
    const float* W_hh0  = (const float*)d_in[4];
    const float* b_hh0  = (const float*)d_in[5];
    const float* W_ih1  = (const float*)d_in[6];
    const float* b_ih1  = (const float*)d_in[7];
    const float* W_hh1  = (const float*)d_in[8];
    const float* b_hh1  = (const float*)d_in[9];
    const float* W_out  = (const float*)d_in[10];
    const float* b_out  = (const float*)d_in[11];
    float* out = (float*)d_out;

    // 1) input projection for all timesteps (parallel, no scan dependency)
    xproj_kernel<<<dim3(8, Tt), 256>>>(x, W_ih0, b_ih0, b_hh0);
    // 2) persistent pipelined scan (one grid barrier per step)
    rnn_kernel<<<G_CTAS, 512>>>(h0, W_hh0, W_ih1, b_ih1, W_hh1, b_hh1);
    // 3) linear head on final top-layer hidden
    head_kernel<<<Bb, Oo>>>(W_out, b_out, out);
}

// round 11
// speedup vs baseline: 1.7517x; 1.7517x over previous
#include <cuda_runtime.h>
#include <math.h>

// Problem dims
#define Tt 1024
#define Bb 64
#define Ii 256
#define Hh 512
#define Oo 128

// Recurrent grid: 43 layer-0 CTAs (12 cols), 86 layer-1 CTAs (6 cols) = 129 CTAs
#define NCTA0 43
#define NC0   12
#define NCTA1 86
#define NC1   6
#define G_CTAS (NCTA0 + NCTA1)

// ---------------- device scratch (no runtime allocation allowed) ----------------
__device__ float g_xproj[(size_t)Tt * Bb * Hh];   // x@W_ih0^T + b_ih0 + b_hh0, [t][b][h]
__device__ float g_h0[2][Bb * Hh];                // double-buffered layer-0 hidden
__device__ float g_h1[2][Bb * Hh];                // double-buffered layer-1 hidden
__device__ unsigned g_flag[G_CTAS * 32];          // per-CTA phase flags, 128B padded

// ---------------- distributed-flag grid barrier (129 co-resident CTAs) ----------
__device__ __forceinline__ unsigned ld_acq(const unsigned* p) {
    unsigned v;
    asm volatile("ld.acquire.gpu.u32 %0, [%1];" : "=r"(v) : "l"(p) : "memory");
    return v;
}
__device__ __forceinline__ void st_rel(unsigned* p, unsigned v) {
    asm volatile("st.relaxed.gpu.u32 [%0], %1;" :: "l"(p), "r"(v) : "memory");
}

// Arrive (publish all this CTA's prior global stores) + wait for all CTAs.
__device__ __forceinline__ void phase_barrier(int cta, unsigned tgt) {
    __syncthreads();                       // all threads' h stores precede (hb)
    if (threadIdx.x == 0) {
        __threadfence();                   // make them gpu-visible
        st_rel(&g_flag[cta * 32], tgt);    // parallel arrival, no atomic serialization
    }
    if (threadIdx.x < G_CTAS) {
        const unsigned* f = &g_flag[threadIdx.x * 32];
        while ((int)(ld_acq(f) - tgt) < 0) { /* L2 round-trip self-throttles */ }
    }
    __syncthreads();
}

// =================================================================================
// Kernel 1: xproj[t][b][j] = sum_i x[b][t][i] * W_ih0[j][i] + b_ih0[j] + b_hh0[j]
// (unchanged — measured at the fp32 FMA roofline, 523us)
// =================================================================================
__global__ void __launch_bounds__(256) xproj_kernel(
    const float* __restrict__ x, const float* __restrict__ W,
    const float* __restrict__ bih, const float* __restrict__ bhh)
{
    __shared__ float xs[64 * 68];
    __shared__ float ws[64 * 68];

    const int t   = blockIdx.y;
    const int n0  = blockIdx.x * 64;
    const int tid = threadIdx.x;
    const int tx  = tid & 15;
    const int ty  = tid >> 4;
    const int mi0 = ty * 4;
    const int ni0 = tx * 4;

    float acc[4][4] = {};

    for (int kc = 0; kc < 4; ++kc) {
        const int k0 = kc * 64;
        for (int idx = tid; idx < 1024; idx += 256) {
            int b  = idx >> 4;
            int c4 = idx & 15;
            float4 v = *reinterpret_cast<const float4*>(
                x + ((size_t)b * Tt + t) * Ii + k0 + c4 * 4);
            *reinterpret_cast<float4*>(xs + b * 68 + c4 * 4) = v;
        }
        for (int idx = tid; idx < 1024; idx += 256) {
            int nl = idx >> 4;
            int c4 = idx & 15;
            float4 v = *reinterpret_cast<const float4*>(
                W + (size_t)(n0 + nl) * Ii + k0 + c4 * 4);
            int k = c4 * 4;
            ws[(k + 0) * 68 + nl] = v.x;
            ws[(k + 1) * 68 + nl] = v.y;
            ws[(k + 2) * 68 + nl] = v.z;
            ws[(k + 3) * 68 + nl] = v.w;
        }
        __syncthreads();
        #pragma unroll 8
        for (int k = 0; k < 64; ++k) {
            float4 wv = *reinterpret_cast<const float4*>(ws + k * 68 + ni0);
            float x0 = xs[(mi0 + 0) * 68 + k];
            float x1 = xs[(mi0 + 1) * 68 + k];
            float x2 = xs[(mi0 + 2) * 68 + k];
            float x3 = xs[(mi0 + 3) * 68 + k];
            acc[0][0] += x0 * wv.x; acc[0][1] += x0 * wv.y; acc[0][2] += x0 * wv.z; acc[0][3] += x0 * wv.w;
            acc[1][0] += x1 * wv.x; acc[1][1] += x1 * wv.y; acc[1][2] += x1 * wv.z; acc[1][3] += x1 * wv.w;
            acc[2][0] += x2 * wv.x; acc[2][1] += x2 * wv.y; acc[2][2] += x2 * wv.z; acc[2][3] += x2 * wv.w;
            acc[3][0] += x3 * wv.x; acc[3][1] += x3 * wv.y; acc[3][2] += x3 * wv.z; acc[3][3] += x3 * wv.w;
        }
        __syncthreads();
    }

    float4 bias;
    bias.x = bih[n0 + ni0 + 0] + bhh[n0 + ni0 + 0];
    bias.y = bih[n0 + ni0 + 1] + bhh[n0 + ni0 + 1];
    bias.z = bih[n0 + ni0 + 2] + bhh[n0 + ni0 + 2];
    bias.w = bih[n0 + ni0 + 3] + bhh[n0 + ni0 + 3];
    #pragma unroll
    for (int i = 0; i < 4; ++i) {
        float4 o;
        o.x = acc[i][0] + bias.x;
        o.y = acc[i][1] + bias.y;
        o.z = acc[i][2] + bias.z;
        o.w = acc[i][3] + bias.w;
        *reinterpret_cast<float4*>(
            g_xproj + ((size_t)t * Bb + (mi0 + i)) * Hh + n0 + ni0) = o;
    }
}

// =================================================================================
// Kernel 2: persistent pipelined scan. One grid barrier per phase.
// Phase p (1..1024):    L0 CTAs: h0(p)   = tanh(xproj[p-1] + h0(p-1)@W_hh0^T)
// Phase p (2..1025):    L1 CTAs: h1(p-1) = tanh(h0(p-1)@W_ih1^T + h1(p-2)@W_hh1^T + b)
// Warp-owns-output GEMV layout: warp w handles batches [4w,4w+4) x all CTA cols,
// lanes split K (coalesced h loads), shfl_xor reduction, no cross-warp traffic.
// =================================================================================
__global__ void __launch_bounds__(512, 1) rnn_kernel(
    const float* __restrict__ h_init,
    const float* __restrict__ W_hh0,
    const float* __restrict__ W_ih1, const float* __restrict__ b_ih1,
    const float* __restrict__ W_hh1, const float* __restrict__ b_hh1)
{
    __shared__ float Wsm[6144];   // L0: [12][512], L1: [6][1024], row-major per col

    const int tid = threadIdx.x;
    const int cta = blockIdx.x;
    const int w   = tid >> 5;
    const int ln  = tid & 31;
    const bool isL0 = (cta < NCTA0);

    const unsigned base = g_flag[cta * 32];   // own last value; uniform across CTAs

    // ---- load weight slice (col-major rows, K contiguous; clamp ragged cols) ----
    if (isL0) {
        const int j0 = cta * NC0;
        float4* W4 = reinterpret_cast<float4*>(Wsm);
        for (int i = tid; i < NC0 * (Hh / 4); i += 512) {
            int c  = i / (Hh / 4);
            int k4 = i % (Hh / 4);
            int col = j0 + c; if (col > Hh - 1) col = Hh - 1;
            W4[i] = *reinterpret_cast<const float4*>(W_hh0 + (size_t)col * Hh + k4 * 4);
        }
    } else {
        const int j0 = (cta - NCTA0) * NC1;
        float4* W4 = reinterpret_cast<float4*>(Wsm);
        for (int i = tid; i < NC1 * (2 * Hh / 4); i += 512) {
            int c  = i / (2 * Hh / 4);
            int k4 = i % (2 * Hh / 4);
            int col = j0 + c; if (col > Hh - 1) col = Hh - 1;
            int k = k4 * 4;
            W4[i] = (k < Hh)
                ? *reinterpret_cast<const float4*>(W_ih1 + (size_t)col * Hh + k)
                : *reinterpret_cast<const float4*>(W_hh1 + (size_t)col * Hh + (k - Hh));
        }
    }
    // ---- init state (graph replays re-init every launch) ----
    for (int i = cta * 512 + tid; i < Bb * Hh; i += G_CTAS * 512) {
        g_h0[0][i] = h_init[i];
        g_h1[0][i] = h_init[Bb * Hh + i];
    }
    phase_barrier(cta, base + 1);   // phase 0: init complete

    const int bq = w * 4;           // this warp's 4 batches

    if (isL0) {
        const int j0 = cta * NC0;
        // lane's epilogue outputs: o0 = ln (always < 48), o1 = ln+32 (if < 48)
        const int o0 = ln;
        const int c0 = o0 >> 2, b0o = o0 & 3;
        const int col0 = j0 + c0;
        const bool v0 = (col0 < Hh);
        const int col0c = v0 ? col0 : Hh - 1;
        const float* xp0 = g_xproj + (size_t)(bq + b0o) * Hh + col0c;

        const int o1 = ln + 32;
        const bool has1 = (o1 < 4 * NC0);
        const int c1 = has1 ? (o1 >> 2) : 0, b1o = o1 & 3;
        const int col1 = j0 + c1;
        const bool v1 = has1 && (col1 < Hh);
        const int col1c = v1 ? col1 : Hh - 1;
        const float* xp1 = g_xproj + (size_t)(bq + b1o) * Hh + col1c;

        for (int p = 1; p <= Tt; ++p) {
            const size_t toff = (size_t)(p - 1) * (Bb * Hh);
            float px0 = __ldcg(xp0 + toff);            // prefetch: hidden under FMA loop
            float px1 = __ldcg(xp1 + toff);
            const float* hprev = g_h0[(p - 1) & 1];
            float*       hout  = g_h0[p & 1];

            float acc[48];
            #pragma unroll
            for (int i = 0; i < 48; ++i) acc[i] = 0.f;

            #pragma unroll 2
            for (int m = 0; m < 4; ++m) {
                const int kk = m * 128 + ln * 4;       // lane-split K, coalesced
                float4 ha = __ldcg(reinterpret_cast<const float4*>(hprev + (bq + 0) * Hh + kk));
                float4 hb = __ldcg(reinterpret_cast<const float4*>(hprev + (bq + 1) * Hh + kk));
                float4 hc = __ldcg(reinterpret_cast<const float4*>(hprev + (bq + 2) * Hh + kk));
                float4 hd = __ldcg(reinterpret_cast<const float4*>(hprev + (bq + 3) * Hh + kk));
                #pragma unroll
                for (int c = 0; c < NC0; ++c) {
                    float4 wv = *reinterpret_cast<const float4*>(Wsm + c * Hh + kk);
                    acc[c*4+0] += ha.x*wv.x + ha.y*wv.y + ha.z*wv.z + ha.w*wv.w;
                    acc[c*4+1] += hb.x*wv.x + hb.y*wv.y + hb.z*wv.z + hb.w*wv.w;
                    acc[c*4+2] += hc.x*wv.x + hc.y*wv.y + hc.z*wv.z + hc.w*wv.w;
                    acc[c*4+3] += hd.x*wv.x + hd.y*wv.y + hd.z*wv.z + hd.w*wv.w;
                }
            }
            // warp-level reduction; extract o0/o1 with compile-time-indexed selects
            float out0 = 0.f, out1 = 0.f;
            #pragma unroll
            for (int i = 0; i < 48; ++i) {
                float v = acc[i];
                v += __shfl_xor_sync(0xffffffffu, v, 16);
                v += __shfl_xor_sync(0xffffffffu, v, 8);
                v += __shfl_xor_sync(0xffffffffu, v, 4);
                v += __shfl_xor_sync(0xffffffffu, v, 2);
                v += __shfl_xor_sync(0xffffffffu, v, 1);
                if (i == o0) out0 = v;
                if (i == o1) out1 = v;
            }
            if (v0) hout[(bq + b0o) * Hh + col0] = tanhf(out0 + px0);
            if (v1) hout[(bq + b1o) * Hh + col1] = tanhf(out1 + px1);

            phase_barrier(cta, base + 1 + p);
        }
        phase_barrier(cta, base + 1 + Tt + 1);   // phase 1025: L1 finishes, L0 idle
    } else {
        const int j0 = (cta - NCTA0) * NC1;
        const int o0 = ln;
        const bool has0 = (o0 < 4 * NC1);        // 24 outputs per warp
        const int c0 = has0 ? (o0 >> 2) : 0, b0o = o0 & 3;
        const int col0 = j0 + c0;
        const bool v0 = has0 && (col0 < Hh);
        const int col0c = v0 ? col0 : Hh - 1;
        const float bias0 = b_ih1[col0c] + b_hh1[col0c];   // hoisted out of the scan

        phase_barrier(cta, base + 2);            // phase 1: idle (wait for h0(1))

        for (int p = 2; p <= Tt + 1; ++p) {
            const float* h0cur  = g_h0[(p - 1) & 1];   // h0(p-1)
            const float* h1prev = g_h1[p & 1];         // h1(p-2)
            float*       hout   = g_h1[(p - 1) & 1];   // h1(p-1)

            float acc[24];
            #pragma unroll
            for (int i = 0; i < 24; ++i) acc[i] = 0.f;

            #pragma unroll 2
            for (int m = 0; m < 8; ++m) {
                const float* src = (m < 4) ? h0cur : h1prev;
                const int kk = (m & 3) * 128 + ln * 4;
                float4 ha = __ldcg(reinterpret_cast<const float4*>(src + (bq + 0) * Hh + kk));
                float4 hb = __ldcg(reinterpret_cast<const float4*>(src + (bq + 1) * Hh + kk));
                float4 hc = __ldcg(reinterpret_cast<const float4*>(src + (bq + 2) * Hh + kk));
                float4 hd = __ldcg(reinterpret_cast<const float4*>(src + (bq + 3) * Hh + kk));
                #pragma unroll
                for (int c = 0; c < NC1; ++c) {
                    float4 wv = *reinterpret_cast<const float4*>(Wsm + c * 1024 + m * 128 + ln * 4);
                    acc[c*4+0] += ha.x*wv.x + ha.y*wv.y + ha.z*wv.z + ha.w*wv.w;
                    acc[c*4+1] += hb.x*wv.x + hb.y*wv.y + hb.z*wv.z + hb.w*wv.w;
                    acc[c*4+2] += hc.x*wv.x + hc.y*wv.y + hc.z*wv.z + hc.w*wv.w;
                    acc[c*4+3] += hd.x*wv.x + hd.y*wv.y + hd.z*wv.z + hd.w*wv.w;
                }
            }
            float out0 = 0.f;
            #pragma unroll
            for (int i = 0; i < 24; ++i) {
                float v = acc[i];
                v += __shfl_xor_sync(0xffffffffu, v, 16);
                v += __shfl_xor_sync(0xffffffffu, v, 8);
                v += __shfl_xor_sync(0xffffffffu, v, 4);
                v += __shfl_xor_sync(0xffffffffu, v, 2);
                v += __shfl_xor_sync(0xffffffffu, v, 1);
                if (i == o0) out0 = v;
            }
            if (v0) hout[(bq + b0o) * Hh + col0] = tanhf(out0 + bias0);

            phase_barrier(cta, base + 1 + p);
        }
    }
}

// =================================================================================
// Kernel 3: out[b][o] = h1_final[b] . W_out[o] + b_out[o]   (h1(1024) is parity 0)
// =================================================================================
__global__ void __launch_bounds__(128) head_kernel(
    const float* __restrict__ W_out, const float* __restrict__ b_out,
    float* __restrict__ out)
{
    const int b = blockIdx.x;
    const int o = threadIdx.x;
    const float* h = g_h1[0] + b * Hh;
    const float* wv = W_out + (size_t)o * Hh;
    float acc = 0.f;
    #pragma unroll 8
    for (int k = 0; k < Hh; k += 4) {
        float4 hv = *reinterpret_cast<const float4*>(h + k);
        float4 wr = *reinterpret_cast<const float4*>(wv + k);
        acc += hv.x * wr.x + hv.y * wr.y + hv.z * wr.z + hv.w * wr.w;
    }
    out[b * Oo + o] = acc + b_out[o];
}

// =================================================================================
extern "C" void kernel_launch(void* const* d_in, const int* in_sizes, int n_in,
                              void* d_out, int out_size)
{
    (void)in_sizes; (void)n_in; (void)out_size;
    const float* x      = (const float*)d_in[0];
    const float* h0     = (const float*)d_in[1];
    const float* W_ih0  = (const float*)d_in[2];
    const float* b_ih0  = (const float*)d_in[3];
    const float* W_hh0  = (const float*)d_in[4];
    const float* b_hh0  = (const float*)d_in[5];
    const float* W_ih1  = (const float*)d_in[6];
    const float* b_ih1  = (const float*)d_in[7];
    const float* W_hh1  = (const float*)d_in[8];
    const float* b_hh1  = (const float*)d_in[9];
    const float* W_out  = (const float*)d_in[10];
    const float* b_out  = (const float*)d_in[11];
    float* out = (float*)d_out;

    xproj_kernel<<<dim3(8, Tt), 256>>>(x, W_ih0, b_ih0, b_hh0);
    rnn_kernel<<<G_CTAS, 512>>>(h0, W_hh0, W_ih1, b_ih1, W_hh1, b_hh1);
    head_kernel<<<Bb, Oo>>>(W_out, b_out, out);
}

// round 12
// speedup vs baseline: 2.0988x; 1.1981x over previous
#include <cuda_runtime.h>
#include <math.h>

// Problem dims
#define Tt 1024
#define Bb 64
#define Ii 256
#define Hh 512
#define Oo 128

// Scan grid: 64 L0 CTAs (16b x 32c, K=512) + 64 L1 CTAs (16b x 32c, K=1024)
#define G_CTAS 128
#define RNN_THREADS 256

// ---------------- device scratch (no runtime allocation allowed) ----------------
__device__ float g_xproj[(size_t)Tt * Bb * Hh];   // x@W_ih0^T + b_ih0 + b_hh0, [t][b][h]
__device__ float g_h0[2][Bb * Hh];                // double-buffered layer-0 hidden
__device__ float g_h1[2][Bb * Hh];                // double-buffered layer-1 hidden
__device__ unsigned g_flag[G_CTAS * 32];          // per-CTA phase flags, 128B padded

// ---------------- packed f32x2 helpers ----------------
#define FMA2(acc, a, b) \
    asm("fma.rn.f32x2 %0, %1, %2, %0;" : "+l"(acc) : "l"(a), "l"(b))

__device__ __forceinline__ float f2sum(unsigned long long u) {
    float lo, hi;
    asm("mov.b64 {%0,%1}, %2;" : "=f"(lo), "=f"(hi) : "l"(u));
    return lo + hi;
}

// ---------------- distributed-flag grid barrier (128 co-resident CTAs) ----------
__device__ __forceinline__ unsigned ld_acq(const unsigned* p) {
    unsigned v;
    asm volatile("ld.acquire.gpu.u32 %0, [%1];" : "=r"(v) : "l"(p) : "memory");
    return v;
}
__device__ __forceinline__ void st_rel(unsigned* p, unsigned v) {
    asm volatile("st.relaxed.gpu.u32 [%0], %1;" :: "l"(p), "r"(v) : "memory");
}

__device__ __forceinline__ void phase_barrier(int cta, unsigned tgt) {
    __syncthreads();
    if (threadIdx.x == 0) {
        __threadfence();
        st_rel(&g_flag[cta * 32], tgt);
    }
    if (threadIdx.x < G_CTAS) {
        const unsigned* f = &g_flag[threadIdx.x * 32];
        while ((int)(ld_acq(f) - tgt) < 0) { }
    }
    __syncthreads();
}

// Multi-value butterfly allreduce: on return v[0] holds, for lane L, the full
// 32-lane sum of original v[L]. 31 shfls total.
__device__ __forceinline__ void butterfly32(float (&v)[32], int ln) {
    #pragma unroll
    for (int m = 16; m >= 1; m >>= 1) {
        #pragma unroll
        for (int i = 0; i < m; ++i) {
            float a = v[i], b = v[i + m];
            float send = (ln & m) ? a : b;
            float recv = __shfl_xor_sync(0xffffffffu, send, m);
            v[i] = (ln & m) ? (b + recv) : (a + recv);
        }
    }
}

// =================================================================================
// Kernel 1: xproj[t][b][j] = sum_i x[b][t][i] * W_ih0[j][i] + b_ih0[j] + b_hh0[j]
// (unchanged — LDS/FMA co-bound at 523us, 7% of total)
// =================================================================================
__global__ void __launch_bounds__(256) xproj_kernel(
    const float* __restrict__ x, const float* __restrict__ W,
    const float* __restrict__ bih, const float* __restrict__ bhh)
{
    __shared__ float xs[64 * 68];
    __shared__ float ws[64 * 68];

    const int t   = blockIdx.y;
    const int n0  = blockIdx.x * 64;
    const int tid = threadIdx.x;
    const int tx  = tid & 15;
    const int ty  = tid >> 4;
    const int mi0 = ty * 4;
    const int ni0 = tx * 4;

    float acc[4][4] = {};

    for (int kc = 0; kc < 4; ++kc) {
        const int k0 = kc * 64;
        for (int idx = tid; idx < 1024; idx += 256) {
            int b  = idx >> 4;
            int c4 = idx & 15;
            float4 v = *reinterpret_cast<const float4*>(
                x + ((size_t)b * Tt + t) * Ii + k0 + c4 * 4);
            *reinterpret_cast<float4*>(xs + b * 68 + c4 * 4) = v;
        }
        for (int idx = tid; idx < 1024; idx += 256) {
            int nl = idx >> 4;
            int c4 = idx & 15;
            float4 v = *reinterpret_cast<const float4*>(
                W + (size_t)(n0 + nl) * Ii + k0 + c4 * 4);
            int k = c4 * 4;
            ws[(k + 0) * 68 + nl] = v.x;
            ws[(k + 1) * 68 + nl] = v.y;
            ws[(k + 2) * 68 + nl] = v.z;
            ws[(k + 3) * 68 + nl] = v.w;
        }
        __syncthreads();
        #pragma unroll 8
        for (int k = 0; k < 64; ++k) {
            float4 wv = *reinterpret_cast<const float4*>(ws + k * 68 + ni0);
            float x0 = xs[(mi0 + 0) * 68 + k];
            float x1 = xs[(mi0 + 1) * 68 + k];
            float x2 = xs[(mi0 + 2) * 68 + k];
            float x3 = xs[(mi0 + 3) * 68 + k];
            acc[0][0] += x0 * wv.x; acc[0][1] += x0 * wv.y; acc[0][2] += x0 * wv.z; acc[0][3] += x0 * wv.w;
            acc[1][0] += x1 * wv.x; acc[1][1] += x1 * wv.y; acc[1][2] += x1 * wv.z; acc[1][3] += x1 * wv.w;
            acc[2][0] += x2 * wv.x; acc[2][1] += x2 * wv.y; acc[2][2] += x2 * wv.z; acc[2][3] += x2 * wv.w;
            acc[3][0] += x3 * wv.x; acc[3][1] += x3 * wv.y; acc[3][2] += x3 * wv.z; acc[3][3] += x3 * wv.w;
        }
        __syncthreads();
    }

    float4 bias;
    bias.x = bih[n0 + ni0 + 0] + bhh[n0 + ni0 + 0];
    bias.y = bih[n0 + ni0 + 1] + bhh[n0 + ni0 + 1];
    bias.z = bih[n0 + ni0 + 2] + bhh[n0 + ni0 + 2];
    bias.w = bih[n0 + ni0 + 3] + bhh[n0 + ni0 + 3];
    #pragma unroll
    for (int i = 0; i < 4; ++i) {
        float4 o;
        o.x = acc[i][0] + bias.x;
        o.y = acc[i][1] + bias.y;
        o.z = acc[i][2] + bias.z;
        o.w = acc[i][3] + bias.w;
        *reinterpret_cast<float4*>(
            g_xproj + ((size_t)t * Bb + (mi0 + i)) * Hh + n0 + ni0) = o;
    }
}

// =================================================================================
// Kernel 2: persistent pipelined scan.
// CTAs 0..63  (L0): tile = batches [16*(cta&3), +16) x cols [32*(cta>>2), +32), K=512
//   phase p (1..1024): h0(p) = tanh(xproj[p-1] + h0(p-1)@W_hh0^T)
// CTAs 64..127 (L1): same tiling, K=1024 ([h0 ; h1] concatenated)
//   phase p (2..1025): h1(p-1) = tanh(h0(p-1)@W_ih1^T + h1(p-2)@W_hh1^T + b)
// Per CTA: weights + h tile staged in SMEM; warp = 8b x 8c tile of f32x2 accs;
// butterfly warp reduction; one grid barrier per phase.
// =================================================================================
extern __shared__ float smf[];

__global__ void __launch_bounds__(RNN_THREADS, 1) rnn_kernel(
    const float* __restrict__ h_init,
    const float* __restrict__ W_hh0,
    const float* __restrict__ W_ih1, const float* __restrict__ b_ih1,
    const float* __restrict__ W_hh1, const float* __restrict__ b_hh1)
{
    const int tid = threadIdx.x;
    const int cta = blockIdx.x;
    const int w   = tid >> 5;
    const int ln  = tid & 31;
    const bool isL0 = (cta < 64);
    const int lcta  = isL0 ? cta : (cta - 64);
    const int B0 = (lcta & 3) * 16;          // batch tile base
    const int j0 = (lcta >> 2) * 32;         // col tile base
    const int lb = (w & 1) * 8;              // warp's local batch base (0/8)
    const int jc = (w >> 1) * 8;             // warp's local col base (0..24)

    const unsigned base = g_flag[cta * 32];

    // lane output mapping: out0 -> (b = ln&7, c = ln>>3), out1 -> (b, c+4)
    const int ob  = ln & 7;
    const int oc  = ln >> 3;
    const int gb  = B0 + lb + ob;
    const int gc0 = j0 + jc + oc;
    const int gc1 = gc0 + 4;

    // ---- SMEM layout ----
    // L0: Wsm [32][512] (16384 f), hs [16][512] (8192 f)
    // L1: Wsm [32][1024] (32768 f), hs0 [16][512], hs1 [16][512]
    float* Wsm = smf;
    float* hs0 = isL0 ? (smf + 16384) : (smf + 32768);
    float* hs1 = smf + 32768 + 8192;   // L1 only

    // ---- load weight tile ----
    if (isL0) {
        float4* Wd = reinterpret_cast<float4*>(Wsm);
        for (int i = tid; i < 32 * 128; i += RNN_THREADS) {
            int c = i >> 7, k4 = i & 127;
            Wd[i] = *reinterpret_cast<const float4*>(W_hh0 + (size_t)(j0 + c) * Hh + k4 * 4);
        }
    } else {
        float4* Wd = reinterpret_cast<float4*>(Wsm);
        for (int i = tid; i < 32 * 256; i += RNN_THREADS) {
            int c = i >> 8, k4 = i & 255;
            Wd[i] = (k4 < 128)
                ? *reinterpret_cast<const float4*>(W_ih1 + (size_t)(j0 + c) * Hh + k4 * 4)
                : *reinterpret_cast<const float4*>(W_hh1 + (size_t)(j0 + c) * Hh + (k4 - 128) * 4);
        }
    }
    // ---- init state from h_init (graph replays re-init every launch) ----
    {
        int i = cta * RNN_THREADS + tid;     // 32768 threads == Bb*Hh elements
        g_h0[0][i] = h_init[i];
        g_h1[0][i] = h_init[Bb * Hh + i];
    }
    phase_barrier(cta, base + 1);            // phase 0: init complete

    if (isL0) {
        const float* xp0 = g_xproj + (size_t)gb * Hh + gc0;
        const float* xp1 = g_xproj + (size_t)gb * Hh + gc1;

        for (int p = 1; p <= Tt; ++p) {
            const float* hprev = g_h0[(p - 1) & 1];
            float*       hout  = g_h0[p & 1];
            const size_t toff  = (size_t)(p - 1) * (Bb * Hh);
            float px0 = __ldcg(xp0 + toff);
            float px1 = __ldcg(xp1 + toff);

            // stage h tile (16 x 512 f = 2048 float4), coalesced
            #pragma unroll
            for (int q = 0; q < 8; ++q) {
                int e = q * 256 + tid;
                int b = e >> 7, k4 = e & 127;
                *reinterpret_cast<float4*>(hs0 + b * 512 + k4 * 4) =
                    __ldcg(reinterpret_cast<const float4*>(hprev + (size_t)(B0 + b) * Hh + k4 * 4));
            }
            __syncthreads();

            unsigned long long acc[64];
            #pragma unroll
            for (int i = 0; i < 64; ++i) acc[i] = 0ull;

            #pragma unroll
            for (int m = 0; m < 4; ++m) {
                const int k = m * 128 + ln * 4;
                ulonglong2 h2[8];
                #pragma unroll
                for (int b = 0; b < 8; ++b)
                    h2[b] = *reinterpret_cast<const ulonglong2*>(hs0 + (lb + b) * 512 + k);
                #pragma unroll
                for (int c = 0; c < 8; ++c) {
                    ulonglong2 w2 = *reinterpret_cast<const ulonglong2*>(Wsm + (jc + c) * 512 + k);
                    #pragma unroll
                    for (int b = 0; b < 8; ++b) {
                        FMA2(acc[c * 8 + b], h2[b].x, w2.x);
                        FMA2(acc[c * 8 + b], h2[b].y, w2.y);
                    }
                }
            }

            float v[32];
            #pragma unroll
            for (int i = 0; i < 32; ++i) v[i] = f2sum(acc[i]);
            butterfly32(v, ln);
            float out0 = v[0];
            #pragma unroll
            for (int i = 0; i < 32; ++i) v[i] = f2sum(acc[32 + i]);
            butterfly32(v, ln);
            float out1 = v[0];

            hout[(size_t)gb * Hh + gc0] = tanhf(out0 + px0);
            hout[(size_t)gb * Hh + gc1] = tanhf(out1 + px1);

            phase_barrier(cta, base + 1 + p);
        }
        phase_barrier(cta, base + 2 + Tt);   // phase 1025: L1 finishes, L0 idle
    } else {
        const float bias0 = b_ih1[gc0] + b_hh1[gc0];
        const float bias1 = b_ih1[gc1] + b_hh1[gc1];

        phase_barrier(cta, base + 2);        // phase 1: idle (waiting for h0(1))

        for (int p = 2; p <= Tt + 1; ++p) {
            const float* h0cur  = g_h0[(p - 1) & 1];   // h0(p-1)
            const float* h1prev = g_h1[p & 1];         // h1(p-2)
            float*       hout   = g_h1[(p - 1) & 1];   // h1(p-1)

            // stage h0 and h1 tiles (2 x 2048 float4)
            #pragma unroll
            for (int q = 0; q < 8; ++q) {
                int e = q * 256 + tid;
                int b = e >> 7, k4 = e & 127;
                *reinterpret_cast<float4*>(hs0 + b * 512 + k4 * 4) =
                    __ldcg(reinterpret_cast<const float4*>(h0cur + (size_t)(B0 + b) * Hh + k4 * 4));
                *reinterpret_cast<float4*>(hs1 + b * 512 + k4 * 4) =
                    __ldcg(reinterpret_cast<const float4*>(h1prev + (size_t)(B0 + b) * Hh + k4 * 4));
            }
            __syncthreads();

            unsigned long long acc[64];
            #pragma unroll
            for (int i = 0; i < 64; ++i) acc[i] = 0ull;

            #pragma unroll
            for (int m = 0; m < 8; ++m) {
                const float* hsrc = (m < 4) ? hs0 : hs1;
                const int k = (m & 3) * 128 + ln * 4;
                ulonglong2 h2[8];
                #pragma unroll
                for (int b = 0; b < 8; ++b)
                    h2[b] = *reinterpret_cast<const ulonglong2*>(hsrc + (lb + b) * 512 + k);
                #pragma unroll
                for (int c = 0; c < 8; ++c) {
                    ulonglong2 w2 = *reinterpret_cast<const ulonglong2*>(
                        Wsm + (jc + c) * 1024 + m * 128 + ln * 4);
                    #pragma unroll
                    for (int b = 0; b < 8; ++b) {
                        FMA2(acc[c * 8 + b], h2[b].x, w2.x);
                        FMA2(acc[c * 8 + b], h2[b].y, w2.y);
                    }
                }
            }

            float v[32];
            #pragma unroll
            for (int i = 0; i < 32; ++i) v[i] = f2sum(acc[i]);
            butterfly32(v, ln);
            float out0 = v[0];
            #pragma unroll
            for (int i = 0; i < 32; ++i) v[i] = f2sum(acc[32 + i]);
            butterfly32(v, ln);
            float out1 = v[0];

            hout[(size_t)gb * Hh + gc0] = tanhf(out0 + bias0);
            hout[(size_t)gb * Hh + gc1] = tanhf(out1 + bias1);

            phase_barrier(cta, base + 1 + p);
        }
    }
}

// =================================================================================
// Kernel 3: out[b][o] = h1_final[b] . W_out[o] + b_out[o]   (h1(1024) is parity 0)
// =================================================================================
__global__ void __launch_bounds__(128) head_kernel(
    const float* __restrict__ W_out, const float* __restrict__ b_out,
    float* __restrict__ out)
{
    const int b = blockIdx.x;
    const int o = threadIdx.x;
    const float* h = g_h1[0] + b * Hh;
    const float* wv = W_out + (size_t)o * Hh;
    float acc = 0.f;
    #pragma unroll 8
    for (int k = 0; k < Hh; k += 4) {
        float4 hv = *reinterpret_cast<const float4*>(h + k);
        float4 wr = *reinterpret_cast<const float4*>(wv + k);
        acc += hv.x * wr.x + hv.y * wr.y + hv.z * wr.z + hv.w * wr.w;
    }
    out[b * Oo + o] = acc + b_out[o];
}

// =================================================================================
extern "C" void kernel_launch(void* const* d_in, const int* in_sizes, int n_in,
                              void* d_out, int out_size)
{
    (void)in_sizes; (void)n_in; (void)out_size;
    const float* x      = (const float*)d_in[0];
    const float* h0     = (const float*)d_in[1];
    const float* W_ih0  = (const float*)d_in[2];
    const float* b_ih0  = (const float*)d_in[3];
    const float* W_hh0  = (const float*)d_in[4];
    const float* b_hh0  = (const float*)d_in[5];
    const float* W_ih1  = (const float*)d_in[6];
    const float* b_ih1  = (const float*)d_in[7];
    const float* W_hh1  = (const float*)d_in[8];
    const float* b_hh1  = (const float*)d_in[9];
    const float* W_out  = (const float*)d_in[10];
    const float* b_out  = (const float*)d_in[11];
    float* out = (float*)d_out;

    // L1 CTAs need 32*1024 + 2*16*512 floats = 49152 f = 192 KB dynamic smem
    static int smem_set = 0;
    if (!smem_set) {
        cudaFuncSetAttribute(rnn_kernel,
                             cudaFuncAttributeMaxDynamicSharedMemorySize, 196608);
        smem_set = 1;
    }

    xproj_kernel<<<dim3(8, Tt), 256>>>(x, W_ih0, b_ih0, b_hh0);
    rnn_kernel<<<G_CTAS, RNN_THREADS, 196608>>>(h0, W_hh0, W_ih1, b_ih1, W_hh1, b_hh1);
    head_kernel<<<Bb, Oo>>>(W_out, b_out, out);
}

// round 13
// speedup vs baseline: 2.4687x; 1.1763x over previous
#include <cuda_runtime.h>
#include <math.h>

// Problem dims
#define Tt 1024
#define Bb 64
#define Ii 256
#define Hh 512
#define Oo 128

// Scan grid: 128 CTAs, each owns 16 batches x 16 cols of BOTH layers
#define G_CTAS 128
#define RNN_THREADS 256

// ---------------- device scratch (no runtime allocation allowed) ----------------
__device__ float g_xproj[(size_t)Tt * Bb * Hh];   // x@W_ih0^T + b_ih0 + b_hh0, [t][b][h]
__device__ float g_h0[2][Bb * Hh];                // double-buffered layer-0 hidden
__device__ float g_h1[2][Bb * Hh];                // double-buffered layer-1 hidden
__device__ unsigned g_flag[G_CTAS * 32];          // per-CTA phase flags, 128B padded

// ---------------- packed f32x2 helpers ----------------
#define FMA2(acc, a, b) \
    asm("fma.rn.f32x2 %0, %1, %2, %0;" : "+l"(acc) : "l"(a), "l"(b))

__device__ __forceinline__ float f2sum(unsigned long long u) {
    float lo, hi;
    asm("mov.b64 {%0,%1}, %2;" : "=f"(lo), "=f"(hi) : "l"(u));
    return lo + hi;
}

// ---------------- cp.async (L2-direct; coherence-safe across SMs) ----------------
__device__ __forceinline__ void cpa16(unsigned s, const float* g) {
    asm volatile("cp.async.cg.shared.global [%0], [%1], 16;" :: "r"(s), "l"(g));
}

// ---------------- distributed-flag grid barrier (128 co-resident CTAs) ----------
__device__ __forceinline__ unsigned ld_acq(const unsigned* p) {
    unsigned v;
    asm volatile("ld.acquire.gpu.u32 %0, [%1];" : "=r"(v) : "l"(p) : "memory");
    return v;
}
__device__ __forceinline__ void st_rel(unsigned* p, unsigned v) {
    asm volatile("st.relaxed.gpu.u32 [%0], %1;" :: "l"(p), "r"(v) : "memory");
}

__device__ __forceinline__ void phase_barrier(int cta, unsigned tgt) {
    __syncthreads();
    if (threadIdx.x == 0) {
        __threadfence();
        st_rel(&g_flag[cta * 32], tgt);
    }
    if (threadIdx.x < G_CTAS) {
        const unsigned* f = &g_flag[threadIdx.x * 32];
        while ((int)(ld_acq(f) - tgt) < 0) { }
    }
    __syncthreads();
}

// Multi-value butterfly allreduce: on return v[0] holds, for lane L, the full
// 32-lane sum of original v[L]. 31 shfls total.
__device__ __forceinline__ void butterfly32(float (&v)[32], int ln) {
    #pragma unroll
    for (int m = 16; m >= 1; m >>= 1) {
        #pragma unroll
        for (int i = 0; i < m; ++i) {
            float a = v[i], b = v[i + m];
            float send = (ln & m) ? a : b;
            float recv = __shfl_xor_sync(0xffffffffu, send, m);
            v[i] = (ln & m) ? (b + recv) : (a + recv);
        }
    }
}

// =================================================================================
// Kernel 1: xproj[t][b][j] = sum_i x[b][t][i] * W_ih0[j][i] + b_ih0[j] + b_hh0[j]
// (unchanged — LDS/FMA co-bound at 523us)
// =================================================================================
__global__ void __launch_bounds__(256) xproj_kernel(
    const float* __restrict__ x, const float* __restrict__ W,
    const float* __restrict__ bih, const float* __restrict__ bhh)
{
    __shared__ float xs[64 * 68];
    __shared__ float ws[64 * 68];

    const int t   = blockIdx.y;
    const int n0  = blockIdx.x * 64;
    const int tid = threadIdx.x;
    const int tx  = tid & 15;
    const int ty  = tid >> 4;
    const int mi0 = ty * 4;
    const int ni0 = tx * 4;

    float acc[4][4] = {};

    for (int kc = 0; kc < 4; ++kc) {
        const int k0 = kc * 64;
        for (int idx = tid; idx < 1024; idx += 256) {
            int b  = idx >> 4;
            int c4 = idx & 15;
            float4 v = *reinterpret_cast<const float4*>(
                x + ((size_t)b * Tt + t) * Ii + k0 + c4 * 4);
            *reinterpret_cast<float4*>(xs + b * 68 + c4 * 4) = v;
        }
        for (int idx = tid; idx < 1024; idx += 256) {
            int nl = idx >> 4;
            int c4 = idx & 15;
            float4 v = *reinterpret_cast<const float4*>(
                W + (size_t)(n0 + nl) * Ii + k0 + c4 * 4);
            int k = c4 * 4;
            ws[(k + 0) * 68 + nl] = v.x;
            ws[(k + 1) * 68 + nl] = v.y;
            ws[(k + 2) * 68 + nl] = v.z;
            ws[(k + 3) * 68 + nl] = v.w;
        }
        __syncthreads();
        #pragma unroll 8
        for (int k = 0; k < 64; ++k) {
            float4 wv = *reinterpret_cast<const float4*>(ws + k * 68 + ni0);
            float x0 = xs[(mi0 + 0) * 68 + k];
            float x1 = xs[(mi0 + 1) * 68 + k];
            float x2 = xs[(mi0 + 2) * 68 + k];
            float x3 = xs[(mi0 + 3) * 68 + k];
            acc[0][0] += x0 * wv.x; acc[0][1] += x0 * wv.y; acc[0][2] += x0 * wv.z; acc[0][3] += x0 * wv.w;
            acc[1][0] += x1 * wv.x; acc[1][1] += x1 * wv.y; acc[1][2] += x1 * wv.z; acc[1][3] += x1 * wv.w;
            acc[2][0] += x2 * wv.x; acc[2][1] += x2 * wv.y; acc[2][2] += x2 * wv.z; acc[2][3] += x2 * wv.w;
            acc[3][0] += x3 * wv.x; acc[3][1] += x3 * wv.y; acc[3][2] += x3 * wv.z; acc[3][3] += x3 * wv.w;
        }
        __syncthreads();
    }

    float4 bias;
    bias.x = bih[n0 + ni0 + 0] + bhh[n0 + ni0 + 0];
    bias.y = bih[n0 + ni0 + 1] + bhh[n0 + ni0 + 1];
    bias.z = bih[n0 + ni0 + 2] + bhh[n0 + ni0 + 2];
    bias.w = bih[n0 + ni0 + 3] + bhh[n0 + ni0 + 3];
    #pragma unroll
    for (int i = 0; i < 4; ++i) {
        float4 o;
        o.x = acc[i][0] + bias.x;
        o.y = acc[i][1] + bias.y;
        o.z = acc[i][2] + bias.z;
        o.w = acc[i][3] + bias.w;
        *reinterpret_cast<float4*>(
            g_xproj + ((size_t)t * Bb + (mi0 + i)) * Hh + n0 + ni0) = o;
    }
}

// =================================================================================
// Kernel 2: persistent merged-layer scan. One grid barrier per phase.
// Phase p (1..1025), CTA (bt=cta>>5, ct=cta&31) owns batches [16bt,+16) x cols
// [16ct,+16) of BOTH layers:
//   warps 0-3: h0(p)   = tanh(xproj[p-1] + h0(p-1)@W_hh0^T)          [p<=1024]
//   warps 4-7: h1(p-1) = tanh(h0(p-1)@W_ih1^T + h1(p-2)@W_hh1^T + b) [p>=2]
// h tiles fetched via cp.async.cg (2 groups: h0 first, h1 lands under Phase A).
// Warp tile = 8b x 8c f32x2 accumulators; butterfly warp reduction.
// =================================================================================
extern __shared__ float smf[];

__global__ void __launch_bounds__(RNN_THREADS, 1) rnn_kernel(
    const float* __restrict__ h_init,
    const float* __restrict__ W_hh0,
    const float* __restrict__ W_ih1, const float* __restrict__ b_ih1,
    const float* __restrict__ W_hh1, const float* __restrict__ b_hh1)
{
    const int tid = threadIdx.x;
    const int cta = blockIdx.x;
    const int w   = tid >> 5;
    const int ln  = tid & 31;
    const int B0  = (cta >> 5) * 16;     // batch tile base
    const int C0  = (cta & 31) * 16;     // col tile base (same cols for L0 & L1)
    const bool isL0w = (w < 4);
    const int wl = isL0w ? w : (w - 4);
    const int lb = (wl & 1) * 8;         // warp local batch base (0/8)
    const int cw = (wl >> 1) * 8;        // warp local col base (0/8)

    // SMEM: W0[16][512] | Wi1[16][512] | Wh1[16][512] | hs0[16][512] | hs1[16][512]
    float* W0  = smf;
    float* Wi1 = smf + 8192;
    float* Wh1 = smf + 16384;
    float* hs0 = smf + 24576;
    float* hs1 = smf + 32768;

    const unsigned base = g_flag[cta * 32];

    // ---- load weight slices (K contiguous per col) ----
    {
        float4* d0 = reinterpret_cast<float4*>(W0);
        float4* d1 = reinterpret_cast<float4*>(Wi1);
        float4* d2 = reinterpret_cast<float4*>(Wh1);
        for (int i = tid; i < 16 * 128; i += RNN_THREADS) {
            int c = i >> 7, k4 = i & 127;
            size_t go = (size_t)(C0 + c) * Hh + k4 * 4;
            d0[i] = *reinterpret_cast<const float4*>(W_hh0 + go);
            d1[i] = *reinterpret_cast<const float4*>(W_ih1 + go);
            d2[i] = *reinterpret_cast<const float4*>(W_hh1 + go);
        }
    }
    // ---- init state (graph replays re-init every launch) ----
    {
        int i = cta * RNN_THREADS + tid;     // 32768 threads == Bb*Hh
        g_h0[0][i] = h_init[i];
        g_h1[0][i] = h_init[Bb * Hh + i];
    }
    phase_barrier(cta, base + 1);            // init complete

    // per-lane output mapping (flat acc idx = b*8+c): out0 b=ln>>3, out1 b=4+(ln>>3)
    const int ob0 = lb + (ln >> 3);
    const int ob1 = ob0 + 4;
    const int gc  = C0 + cw + (ln & 7);
    const float bias1 = b_ih1[gc] + b_hh1[gc];               // L1 warps only
    const float* xpa = g_xproj + (size_t)(B0 + ob0) * Hh + gc;
    const float* xpb = g_xproj + (size_t)(B0 + ob1) * Hh + gc;

    const unsigned hs0u = (unsigned)__cvta_generic_to_shared(hs0);
    const unsigned hs1u = (unsigned)__cvta_generic_to_shared(hs1);
    const int bhi = tid >> 7;                // stage addressing
    const int k4s = tid & 127;

    for (int p = 1; p <= Tt + 1; ++p) {
        const float* h0prev = g_h0[(p - 1) & 1];   // h0(p-1)
        float*       h0out  = g_h0[p & 1];         // h0(p)
        const float* h1prev = g_h1[p & 1];         // h1(p-2)
        float*       h1out  = g_h1[(p - 1) & 1];   // h1(p-1)

        float px0 = 0.f, px1 = 0.f;
        if (isL0w && p <= Tt) {                    // DRAM prefetch, hidden by FMAs
            size_t toff = (size_t)(p - 1) * (Bb * Hh);
            px0 = __ldcg(xpa + toff);
            px1 = __ldcg(xpb + toff);
        }

        // async stage: group A = h0 tile, group B = h1 tile (16B chunks)
        #pragma unroll
        for (int q = 0; q < 8; ++q) {
            int b = q * 2 + bhi;
            cpa16(hs0u + (unsigned)(b * 512 + k4s * 4) * 4u,
                  h0prev + (size_t)(B0 + b) * Hh + k4s * 4);
        }
        asm volatile("cp.async.commit_group;");
        #pragma unroll
        for (int q = 0; q < 8; ++q) {
            int b = q * 2 + bhi;
            cpa16(hs1u + (unsigned)(b * 512 + k4s * 4) * 4u,
                  h1prev + (size_t)(B0 + b) * Hh + k4s * 4);
        }
        asm volatile("cp.async.commit_group;");

        unsigned long long acc[64];
        #pragma unroll
        for (int i = 0; i < 64; ++i) acc[i] = 0ull;

        asm volatile("cp.async.wait_group 1;" ::: "memory");   // h0 tile ready
        __syncthreads();

        // ---- Phase A: all warps consume h0(p-1) ----
        const float* Wa = isL0w ? W0 : Wi1;
        #pragma unroll
        for (int m = 0; m < 4; ++m) {
            const int k = m * 128 + ln * 4;
            ulonglong2 h2[8];
            #pragma unroll
            for (int b = 0; b < 8; ++b)
                h2[b] = *reinterpret_cast<const ulonglong2*>(hs0 + (lb + b) * 512 + k);
            #pragma unroll
            for (int c = 0; c < 8; ++c) {
                ulonglong2 w2 = *reinterpret_cast<const ulonglong2*>(Wa + (cw + c) * 512 + k);
                #pragma unroll
                for (int b = 0; b < 8; ++b) {
                    FMA2(acc[b * 8 + c], h2[b].x, w2.x);
                    FMA2(acc[b * 8 + c], h2[b].y, w2.y);
                }
            }
        }

        asm volatile("cp.async.wait_group 0;" ::: "memory");   // h1 tile ready
        __syncthreads();

        // ---- Phase B: L1 warps consume h1(p-2) ----
        if (!isL0w && p > 1) {
            #pragma unroll
            for (int m = 0; m < 4; ++m) {
                const int k = m * 128 + ln * 4;
                ulonglong2 h2[8];
                #pragma unroll
                for (int b = 0; b < 8; ++b)
                    h2[b] = *reinterpret_cast<const ulonglong2*>(hs1 + (lb + b) * 512 + k);
                #pragma unroll
                for (int c = 0; c < 8; ++c) {
                    ulonglong2 w2 = *reinterpret_cast<const ulonglong2*>(Wh1 + (cw + c) * 512 + k);
                    #pragma unroll
                    for (int b = 0; b < 8; ++b) {
                        FMA2(acc[b * 8 + c], h2[b].x, w2.x);
                        FMA2(acc[b * 8 + c], h2[b].y, w2.y);
                    }
                }
            }
        }

        // ---- reduce + activation + store ----
        float v[32];
        #pragma unroll
        for (int i = 0; i < 32; ++i) v[i] = f2sum(acc[i]);
        butterfly32(v, ln);
        float out0 = v[0];
        #pragma unroll
        for (int i = 0; i < 32; ++i) v[i] = f2sum(acc[32 + i]);
        butterfly32(v, ln);
        float out1 = v[0];

        if (isL0w) {
            if (p <= Tt) {
                h0out[(size_t)(B0 + ob0) * Hh + gc] = tanhf(out0 + px0);
                h0out[(size_t)(B0 + ob1) * Hh + gc] = tanhf(out1 + px1);
            }
        } else if (p > 1) {
            h1out[(size_t)(B0 + ob0) * Hh + gc] = tanhf(out0 + bias1);
            h1out[(size_t)(B0 + ob1) * Hh + gc] = tanhf(out1 + bias1);
        }

        phase_barrier(cta, base + 1 + p);
    }
}

// =================================================================================
// Kernel 3: out[b][o] = h1_final[b] . W_out[o] + b_out[o]   (h1(1024) is parity 0)
// =================================================================================
__global__ void __launch_bounds__(128) head_kernel(
    const float* __restrict__ W_out, const float* __restrict__ b_out,
    float* __restrict__ out)
{
    const int b = blockIdx.x;
    const int o = threadIdx.x;
    const float* h = g_h1[0] + b * Hh;
    const float* wv = W_out + (size_t)o * Hh;
    float acc = 0.f;
    #pragma unroll 8
    for (int k = 0; k < Hh; k += 4) {
        float4 hv = *reinterpret_cast<const float4*>(h + k);
        float4 wr = *reinterpret_cast<const float4*>(wv + k);
        acc += hv.x * wr.x + hv.y * wr.y + hv.z * wr.z + hv.w * wr.w;
    }
    out[b * Oo + o] = acc + b_out[o];
}

// =================================================================================
extern "C" void kernel_launch(void* const* d_in, const int* in_sizes, int n_in,
                              void* d_out, int out_size)
{
    (void)in_sizes; (void)n_in; (void)out_size;
    const float* x      = (const float*)d_in[0];
    const float* h0     = (const float*)d_in[1];
    const float* W_ih0  = (const float*)d_in[2];
    const float* b_ih0  = (const float*)d_in[3];
    const float* W_hh0  = (const float*)d_in[4];
    const float* b_hh0  = (const float*)d_in[5];
    const float* W_ih1  = (const float*)d_in[6];
    const float* b_ih1  = (const float*)d_in[7];
    const float* W_hh1  = (const float*)d_in[8];
    const float* b_hh1  = (const float*)d_in[9];
    const float* W_out  = (const float*)d_in[10];
    const float* b_out  = (const float*)d_in[11];
    float* out = (float*)d_out;

    // SMEM: 3x(16x512) weights + 2x(16x512) h tiles = 40960 floats = 160 KB
    static int smem_set = 0;
    if (!smem_set) {
        cudaFuncSetAttribute(rnn_kernel,
                             cudaFuncAttributeMaxDynamicSharedMemorySize, 163840);
        smem_set = 1;
    }

    xproj_kernel<<<dim3(8, Tt), 256>>>(x, W_ih0, b_ih0, b_hh0);
    rnn_kernel<<<G_CTAS, RNN_THREADS, 163840>>>(h0, W_hh0, W_ih1, b_ih1, W_hh1, b_hh1);
    head_kernel<<<Bb, Oo>>>(W_out, b_out, out);
}